// round 2
// baseline (speedup 1.0000x reference)
#include <cuda_runtime.h>
#include <math.h>

#define NMAX 20000
#define CDIM 64
#define NLMD 9
#define NBES 8
#define ZDIM 10

// ---------------- scratch (device globals; no allocation) ----------------
__device__ float g_msg[NMAX * NLMD * CDIM];   // [N][lm][c]  46.08 MB
__device__ float g_htable[ZDIM * CDIM];       // per-species embedding row
__device__ float g_xout[NMAX * CDIM];         // contraction result

// ---------------- zero the message buffer ----------------
__global__ void zero_msg_kernel(int n4) {
  int i = blockIdx.x * blockDim.x + threadIdx.x;
  float4* p = reinterpret_cast<float4*>(g_msg);
  if (i < n4) p[i] = make_float4(0.f, 0.f, 0.f, 0.f);
}

// ---------------- species embedding table: (W_embed[z]/sqrt(Z)) @ W_up / sqrt(C) ----------------
__global__ void htable_kernel(const float* __restrict__ W_embed,
                              const float* __restrict__ W_up) {
  int t = threadIdx.x;
  if (t < ZDIM * CDIM) {
    int z = t >> 6, c = t & 63;
    float acc = 0.f;
    #pragma unroll 8
    for (int k = 0; k < CDIM; k++)
      acc = fmaf(W_embed[z * CDIM + k], W_up[k * CDIM + c], acc);
    g_htable[t] = acc * (1.0f / (3.16227766016838f * 8.0f));  // /(sqrt(10)*sqrt(64))
  }
}

// ---------------- fused edge kernel ----------------
// One block == 128 edges. All MLP weights + activations in shared memory.
struct ESmem {
  float w1[NBES * CDIM];   // 512
  float w2[CDIM * CDIM];   // 4096
  float w3[CDIM * CDIM];   // 4096
  float w4[CDIM * 192];    // 12288
  float htab[ZDIM * CDIM]; // 640
  float EF[128 * 9];       // edge feats (8 used, stride 9)
  float Fa[128 * 68];      // activation ping (stride 68: float4-aligned, bank-safe)
  float Fb[128 * 68];      // activation pong
  float Yb[128 * 9];       // spherical harmonics
  int   recv[128];
  int   zs[128];           // sender species
};

// C[128x64] = act(A[128xK] @ B[K x *] cols [Bc0, Bc0+64)), C stride 68.
// Thread map: rg = tid>>4 (rows rg+16*i), cg = tid&15 (cols cg*4..+3).
template <int K, bool ACT>
__device__ __forceinline__ void gemm128(const float* __restrict__ A, int As,
                                        const float* __restrict__ B, int Bs, int Bc0,
                                        float* __restrict__ Cm, int tid) {
  int rg = tid >> 4, cg = tid & 15;
  float acc[8][4];
  #pragma unroll
  for (int i = 0; i < 8; i++) { acc[i][0] = 0.f; acc[i][1] = 0.f; acc[i][2] = 0.f; acc[i][3] = 0.f; }
  #pragma unroll 4
  for (int k = 0; k < K; k++) {
    float4 b = *reinterpret_cast<const float4*>(B + k * Bs + Bc0 + cg * 4);
    #pragma unroll
    for (int i = 0; i < 8; i++) {
      float a = A[(rg + 16 * i) * As + k];
      acc[i][0] = fmaf(a, b.x, acc[i][0]);
      acc[i][1] = fmaf(a, b.y, acc[i][1]);
      acc[i][2] = fmaf(a, b.z, acc[i][2]);
      acc[i][3] = fmaf(a, b.w, acc[i][3]);
    }
  }
  #pragma unroll
  for (int i = 0; i < 8; i++) {
    float vv0 = acc[i][0], vv1 = acc[i][1], vv2 = acc[i][2], vv3 = acc[i][3];
    if (ACT) {
      vv0 = vv0 / (1.0f + __expf(-vv0));
      vv1 = vv1 / (1.0f + __expf(-vv1));
      vv2 = vv2 / (1.0f + __expf(-vv2));
      vv3 = vv3 / (1.0f + __expf(-vv3));
    }
    *reinterpret_cast<float4*>(Cm + (rg + 16 * i) * 68 + cg * 4) =
        make_float4(vv0, vv1, vv2, vv3);
  }
}

extern __shared__ float esmem_raw[];

__global__ void __launch_bounds__(256, 1)
edge_kernel(const float* __restrict__ pos, const int* __restrict__ ai,
            const int* __restrict__ ei,
            const float* __restrict__ w1, const float* __restrict__ w2,
            const float* __restrict__ w3, const float* __restrict__ w4, int E) {
  ESmem& s = *reinterpret_cast<ESmem*>(esmem_raw);
  int tid = threadIdx.x;

  // stage weights + species table (L2-resident; 82.5 KB per block)
  {
    float4* d; const float4* g;
    d = (float4*)s.w1;   g = (const float4*)w1;        for (int i = tid; i < NBES * CDIM / 4; i += 256) d[i] = g[i];
    d = (float4*)s.w2;   g = (const float4*)w2;        for (int i = tid; i < CDIM * CDIM / 4; i += 256) d[i] = g[i];
    d = (float4*)s.w3;   g = (const float4*)w3;        for (int i = tid; i < CDIM * CDIM / 4; i += 256) d[i] = g[i];
    d = (float4*)s.w4;   g = (const float4*)w4;        for (int i = tid; i < CDIM * 192 / 4; i += 256) d[i] = g[i];
    d = (float4*)s.htab; g = (const float4*)g_htable;  for (int i = tid; i < ZDIM * CDIM / 4; i += 256) d[i] = g[i];
  }

  // geometry: radial basis + cutoff + spherical harmonics
  if (tid < 128) {
    int eg = blockIdx.x * 128 + tid;
    float* Y  = s.Yb + tid * 9;
    float* ef = s.EF + tid * 9;
    if (eg < E) {
      int sd = ei[eg];
      int rv = ei[E + eg];
      float px = pos[3 * rv + 0] - pos[3 * sd + 0];
      float py = pos[3 * rv + 1] - pos[3 * sd + 1];
      float pz = pos[3 * rv + 2] - pos[3 * sd + 2];
      float r2 = px * px + py * py + pz * pz + 1e-12f;
      float r = sqrtf(r2);
      float inv = 1.0f / r;
      float ux = px * inv, uy = py * inv, uz = pz * inv;
      const float c3 = 1.73205080756888f;   // sqrt(3)
      const float c5 = 2.23606797749979f;   // sqrt(5)
      const float c15 = 3.87298334620742f;  // sqrt(15)
      Y[0] = 1.0f;
      Y[1] = c3 * ux; Y[2] = c3 * uy; Y[3] = c3 * uz;
      Y[4] = c15 * ux * uy; Y[5] = c15 * uy * uz;
      Y[6] = 0.5f * c5 * (3.0f * uz * uz - 1.0f);
      Y[7] = c15 * ux * uz;
      Y[8] = 0.5f * c15 * (ux * ux - uy * uy);
      float u = fminf(r * 0.2f, 1.0f);            // r/RMAX
      float u2 = u * u, u4 = u2 * u2, u6 = u4 * u2, u7 = u6 * u, u8 = u4 * u4;
      float fc = 1.0f - 28.0f * u6 + 48.0f * u7 - 21.0f * u8;  // p=6 polynomial cutoff
      float pref = 0.632455532033676f * inv * fc;  // sqrt(2/RMAX)/r * fcut
      float w = 0.628318530717958648f * r;         // pi*r/RMAX
      #pragma unroll
      for (int nb = 1; nb <= 8; nb++) ef[nb - 1] = pref * sinf(w * (float)nb);
      s.recv[tid] = rv;
      s.zs[tid] = ai[sd];
    } else {
      #pragma unroll
      for (int q = 0; q < 9; q++) Y[q] = 0.f;
      #pragma unroll
      for (int q = 0; q < 8; q++) ef[q] = 0.f;
      s.recv[tid] = -1;
      s.zs[tid] = 0;
    }
  }
  __syncthreads();

  gemm128<8,  true >(s.EF, 9,  s.w1, 64, 0, s.Fa, tid); __syncthreads();
  gemm128<64, true >(s.Fa, 68, s.w2, 64, 0, s.Fb, tid); __syncthreads();
  gemm128<64, true >(s.Fb, 68, s.w3, 64, 0, s.Fa, tid); __syncthreads();

  // layer 4 in 3 column-chunks (the 3 l-channels), each followed by scatter
  int wid = tid >> 5, lane = tid & 31;
  #pragma unroll
  for (int l = 0; l < 3; l++) {
    gemm128<64, false>(s.Fa, 68, s.w4, 192, l * 64, s.Fb, tid);
    __syncthreads();
    int lm0 = (l == 0) ? 0 : ((l == 1) ? 1 : 4);
    int cnt = (l == 0) ? 1 : ((l == 1) ? 3 : 5);
    for (int e = wid; e < 128; e += 8) {
      int rv = s.recv[e];
      if (rv >= 0) {
        int zz = s.zs[e];
        #pragma unroll
        for (int half = 0; half < 2; half++) {
          int c = lane + 32 * half;
          float val = s.htab[zz * 64 + c] * s.Fb[e * 68 + c];
          float* mp = g_msg + rv * 576 + c;
          for (int q = 0; q < cnt; q++)
            atomicAdd(mp + (lm0 + q) * 64, val * s.Yb[e * 9 + lm0 + q]);
        }
      }
    }
    __syncthreads();
  }
}

// ---------------- per-(node,channel) tensor contraction ----------------
__global__ void __launch_bounds__(256)
contract_kernel(const int* __restrict__ ai,
                const float* __restrict__ U3, const float* __restrict__ U2,
                const float* __restrict__ U1,
                const float* __restrict__ Wc3, const float* __restrict__ Wc2,
                const float* __restrict__ Wc1, int N) {
  __shared__ float4 sU3[729];  // [i][j][k] x p
  __shared__ float4 sU2[81];
  __shared__ float4 sU1[9];
  __shared__ float sW3[ZDIM * 4 * CDIM];
  __shared__ float sW2[ZDIM * 4 * CDIM];
  __shared__ float sW1[ZDIM * 4 * CDIM];
  int tid = threadIdx.x;
  for (int i = tid; i < 729; i += 256) sU3[i] = ((const float4*)U3)[i];
  for (int i = tid; i < 81;  i += 256) sU2[i] = ((const float4*)U2)[i];
  if (tid < 9) sU1[tid] = ((const float4*)U1)[tid];
  for (int i = tid; i < ZDIM * 64; i += 256) {
    ((float4*)sW3)[i] = ((const float4*)Wc3)[i];
    ((float4*)sW2)[i] = ((const float4*)Wc2)[i];
    ((float4*)sW1)[i] = ((const float4*)Wc1)[i];
  }
  __syncthreads();

  int idx = blockIdx.x * 256 + tid;
  if (idx >= N * 64) return;
  int n = idx >> 6, c = idx & 63;
  int z = ai[n];

  float x[9];
  const float* mrow = g_msg + n * 576 + c;
  #pragma unroll
  for (int i = 0; i < 9; i++) x[i] = mrow[i * 64] * (1.0f / 16.0f);  // /AVG

  float w3p[4], w2p[4], w1p[4];
  #pragma unroll
  for (int p = 0; p < 4; p++) {
    w3p[p] = sW3[z * 256 + p * 64 + c];
    w2p[p] = sW2[z * 256 + p * 64 + c];
    w1p[p] = sW1[z * 256 + p * 64 + c];
  }
  float xw[9][4];
  #pragma unroll
  for (int i = 0; i < 9; i++) {
    xw[i][0] = x[i] * w3p[0]; xw[i][1] = x[i] * w3p[1];
    xw[i][2] = x[i] * w3p[2]; xw[i][3] = x[i] * w3p[3];
  }

  float res = 0.f;
  for (int j = 0; j < 9; j++) {
    float vj = 0.f;
    for (int k = 0; k < 9; k++) {
      float4 u2 = sU2[j * 9 + k];
      float t = u2.x * w2p[0] + u2.y * w2p[1] + u2.z * w2p[2] + u2.w * w2p[3];
      #pragma unroll
      for (int i = 0; i < 9; i++) {
        float4 u3 = sU3[i * 81 + j * 9 + k];
        t = fmaf(u3.x, xw[i][0], t);
        t = fmaf(u3.y, xw[i][1], t);
        t = fmaf(u3.z, xw[i][2], t);
        t = fmaf(u3.w, xw[i][3], t);
      }
      vj = fmaf(t, x[k], vj);  // c2[j,k] * x[k]
    }
    float4 u1 = sU1[j];
    vj += u1.x * w1p[0] + u1.y * w1p[1] + u1.z * w1p[2] + u1.w * w1p[3];
    res = fmaf(vj, x[j], res);  // c1[j] * x[j]
  }
  g_xout[idx] = res;
}

// ---------------- final output GEMM: out = xout @ W_out / 8 ----------------
__global__ void __launch_bounds__(256)
out_kernel(const float* __restrict__ W_out, float* __restrict__ out, int N) {
  __shared__ float sW[64 * 64];
  __shared__ float sX[64 * 68];
  int tid = threadIdx.x;
  int n0 = blockIdx.x * 64;
  for (int i = tid; i < 1024; i += 256) ((float4*)sW)[i] = ((const float4*)W_out)[i];
  for (int i = tid; i < 64 * 16; i += 256) {
    int r = i >> 4, c4 = i & 15;
    float4 v = make_float4(0.f, 0.f, 0.f, 0.f);
    if (n0 + r < N) v = *reinterpret_cast<const float4*>(g_xout + (n0 + r) * 64 + c4 * 4);
    *reinterpret_cast<float4*>(sX + r * 68 + c4 * 4) = v;
  }
  __syncthreads();
  int rg = tid >> 4, cg = tid & 15;
  float acc[4][4];
  #pragma unroll
  for (int i = 0; i < 4; i++) { acc[i][0] = 0.f; acc[i][1] = 0.f; acc[i][2] = 0.f; acc[i][3] = 0.f; }
  #pragma unroll 4
  for (int k = 0; k < 64; k++) {
    float4 b = *reinterpret_cast<const float4*>(sW + k * 64 + cg * 4);
    #pragma unroll
    for (int i = 0; i < 4; i++) {
      float a = sX[(rg + 16 * i) * 68 + k];
      acc[i][0] = fmaf(a, b.x, acc[i][0]);
      acc[i][1] = fmaf(a, b.y, acc[i][1]);
      acc[i][2] = fmaf(a, b.z, acc[i][2]);
      acc[i][3] = fmaf(a, b.w, acc[i][3]);
    }
  }
  #pragma unroll
  for (int i = 0; i < 4; i++) {
    int n = n0 + rg + 16 * i;
    if (n < N) {
      *reinterpret_cast<float4*>(out + n * 64 + cg * 4) =
          make_float4(acc[i][0] * 0.125f, acc[i][1] * 0.125f,
                      acc[i][2] * 0.125f, acc[i][3] * 0.125f);
    }
  }
}

// ---------------- launch ----------------
extern "C" void kernel_launch(void* const* d_in, const int* in_sizes, int n_in,
                              void* d_out, int out_size) {
  const float* positions = (const float*)d_in[0];
  const int*   ai        = (const int*)d_in[1];
  const int*   ei        = (const int*)d_in[2];
  const float* W_embed   = (const float*)d_in[3];
  const float* W_up      = (const float*)d_in[4];
  const float* w1        = (const float*)d_in[5];
  const float* w2        = (const float*)d_in[6];
  const float* w3        = (const float*)d_in[7];
  const float* w4        = (const float*)d_in[8];
  const float* U3        = (const float*)d_in[9];
  const float* U2        = (const float*)d_in[10];
  const float* U1        = (const float*)d_in[11];
  const float* Wc3       = (const float*)d_in[12];
  const float* Wc2       = (const float*)d_in[13];
  const float* Wc1       = (const float*)d_in[14];
  const float* W_out     = (const float*)d_in[15];
  float* out = (float*)d_out;

  int N = in_sizes[0] / 3;
  int E = in_sizes[2] / 2;

  cudaFuncSetAttribute(edge_kernel, cudaFuncAttributeMaxDynamicSharedMemorySize,
                       (int)sizeof(ESmem));

  int msg4 = (N * 576) / 4;
  zero_msg_kernel<<<(msg4 + 255) / 256, 256>>>(msg4);
  htable_kernel<<<1, 640>>>(W_embed, W_up);
  int ntiles = (E + 127) / 128;
  edge_kernel<<<ntiles, 256, sizeof(ESmem)>>>(positions, ai, ei, w1, w2, w3, w4, E);
  int nc = N * 64;
  contract_kernel<<<(nc + 255) / 256, 256>>>(ai, U3, U2, U1, Wc3, Wc2, Wc1, N);
  out_kernel<<<(N + 63) / 64, 256>>>(W_out, out, N);

  (void)n_in; (void)out_size;
}